// round 16
// baseline (speedup 1.0000x reference)
#include <cuda_runtime.h>
#include <cuda_bf16.h>
#include <math.h>

// ---------------- problem constants ----------------
#define NB    8
#define CCH   256
#define HH    128
#define WW2   128
#define HWP   (HH*WW2)          // 16384
#define TOK0  (NB*HH*WW2)       // 131072 tokens level-0
#define H1    32
#define TOK1  (NB*H1*H1)        // 8192 tokens level-1
#define HEADS 8
#define DH    32
#define DF    1024

// ---------------- device scratch (static; allocation-free) ----------------
__device__ float g_xh   [(size_t)TOK0*CCH];
__device__ float g_q    [(size_t)TOK0*CCH];
__device__ float g_k    [(size_t)TOK0*CCH];
__device__ float g_v    [(size_t)TOK0*CCH];
__device__ float g_attn [(size_t)TOK0*CCH];
__device__ float g_proj [(size_t)TOK0*CCH];
__device__ float g_l0   [(size_t)TOK0*CCH];
__device__ float g_lc   [(size_t)TOK0*CCH];
__device__ float g_hid  [(size_t)TOK0*DF];
__device__ float g_pool [(size_t)TOK1*CCH];
__device__ float g_q1   [(size_t)TOK1*CCH];
__device__ float g_k1   [(size_t)TOK1*CCH];
__device__ float g_v1   [(size_t)TOK1*CCH];
__device__ float g_a1   [(size_t)TOK1*CCH];
__device__ float g_p1   [(size_t)TOK1*CCH];
__device__ float g_l1   [(size_t)TOK1*CCH];

// pre-split weights (bf16 hi/lo), one linear arena
#define OFF_SAWQ  0
#define OFF_SAWK  65536
#define OFF_SAWV  131072
#define OFF_SAWF  196608
#define OFF_CAWQ  262144
#define OFF_CAWK  327680
#define OFF_CAWV  393216
#define OFF_CAWF  458752
#define OFF_FFN1  524288
#define OFF_FFN2  786432
#define WTOT      1048576
__device__ __align__(16) __nv_bfloat16 g_wh[WTOT];
__device__ __align__(16) __nv_bfloat16 g_wl[WTOT];

// ---------------- transposes (NCHW <-> NHWC) ----------------
__global__ void transpose_in_k(const float* __restrict__ in, float* __restrict__ out) {
    __shared__ float tile[32][33];
    int n  = blockIdx.z;
    int p0 = blockIdx.x * 32;
    int c0 = blockIdx.y * 32;
    for (int j = threadIdx.y; j < 32; j += 8)
        tile[j][threadIdx.x] = in[((size_t)(n*CCH + c0 + j))*HWP + p0 + threadIdx.x];
    __syncthreads();
    for (int j = threadIdx.y; j < 32; j += 8)
        out[((size_t)(n*HWP + p0 + j))*CCH + c0 + threadIdx.x] = tile[threadIdx.x][j];
}

__global__ void transpose_out_k(const float* __restrict__ in, float* __restrict__ out) {
    __shared__ float tile[32][33];
    int n  = blockIdx.z;
    int p0 = blockIdx.x * 32;
    int c0 = blockIdx.y * 32;
    for (int j = threadIdx.y; j < 32; j += 8)
        tile[j][threadIdx.x] = in[((size_t)(n*HWP + p0 + j))*CCH + c0 + threadIdx.x];
    __syncthreads();
    for (int j = threadIdx.y; j < 32; j += 8)
        out[((size_t)(n*CCH + c0 + j))*HWP + p0 + threadIdx.x] = tile[threadIdx.x][j];
}

// ---------------- weight split: all 10 matrices in ONE launch --------------
__device__ __forceinline__ void bsplit(float x, __nv_bfloat16& h, __nv_bfloat16& l) {
    h = __float2bfloat16(x);
    l = __float2bfloat16(x - __bfloat162float(h));
}

struct WJobs { const float* p[10]; };

__global__ void wsplit_all_k(WJobs jobs, __nv_bfloat16* __restrict__ hi,
                             __nv_bfloat16* __restrict__ lo) {
    int i = blockIdx.x * 256 + threadIdx.x;
    if (i >= WTOT) return;
    int seg, off;
    if (i < 524288) { seg = i >> 16;             off = i & 65535;  }
    else            { int j = i - 524288; seg = 8 + (j >> 18); off = j & 262143; }
    __nv_bfloat16 h, l;
    bsplit(jobs.p[seg][off], h, l);
    hi[i] = h; lo[i] = l;
}

// ---------------- bf16x3 split tensor-core GEMM (pre-split B) --------------
// C[M,N] = A[M,K] @ B[K,N] (+bias)(+relu); B given pre-split as bf16 hi/lo.
// Block 128x128x16, 256 threads, 8 warps of 32x64 warp tiles.
// A: single-buffered smem, in-loop split (register prefetch, as in R9/R14).
// B: DOUBLE-buffered smem via cp.async, issued after first barrier ->
//    overlaps the MMA body. No B registers, no B split ALU.

#define LDSM_X4(r, addr) \
    asm volatile("ldmatrix.sync.aligned.m8n8.x4.shared.b16 {%0,%1,%2,%3}, [%4];" \
        : "=r"(r[0]), "=r"(r[1]), "=r"(r[2]), "=r"(r[3]) : "r"(addr))

#define LDSM_X4_T(r, addr) \
    asm volatile("ldmatrix.sync.aligned.m8n8.x4.trans.shared.b16 {%0,%1,%2,%3}, [%4];" \
        : "=r"(r[0]), "=r"(r[1]), "=r"(r[2]), "=r"(r[3]) : "r"(addr))

#define MMA_BF16(d, a, b0_, b1_) \
    asm volatile("mma.sync.aligned.m16n8k16.row.col.f32.bf16.bf16.f32 " \
        "{%0,%1,%2,%3}, {%4,%5,%6,%7}, {%8,%9}, {%0,%1,%2,%3};" \
        : "+f"(d[0]), "+f"(d[1]), "+f"(d[2]), "+f"(d[3]) \
        : "r"(a[0]), "r"(a[1]), "r"(a[2]), "r"(a[3]), "r"(b0_), "r"(b1_))

#define CP_ASYNC16(dst, src) \
    asm volatile("cp.async.ca.shared.global [%0], [%1], 16;" :: "r"(dst), "l"(src))
#define CP_COMMIT() asm volatile("cp.async.commit_group;")
#define CP_WAIT0()  asm volatile("cp.async.wait_group 0;")

#define A_STRIDE 24    // 16 used + 8 pad bf16 -> 48B rows, conflict-free ldmatrix
#define B_STRIDE 136   // 128 used + 8 pad bf16 -> 272B rows (16B-aligned: 272=16*17)

template<bool RELU, bool BIAS>
__global__ __launch_bounds__(256, 2)
void gemm_mma_k(const float* __restrict__ A,
                const __nv_bfloat16* __restrict__ Bh_g,
                const __nv_bfloat16* __restrict__ Bl_g,
                const float* __restrict__ bias, float* __restrict__ C,
                int M, int N, int K) {
    __shared__ __align__(16) __nv_bfloat16 Ah[128][A_STRIDE];
    __shared__ __align__(16) __nv_bfloat16 Al[128][A_STRIDE];
    __shared__ __align__(16) __nv_bfloat16 Bh[2][16][B_STRIDE];
    __shared__ __align__(16) __nv_bfloat16 Bl[2][16][B_STRIDE];

    int tid  = threadIdx.x;
    int lane = tid & 31;
    int wid  = tid >> 5;
    int m0 = blockIdx.y * 128, n0b = blockIdx.x * 128;

    int rm = (wid & 3) * 32;        // warp row base
    int rn = (wid >> 2) * 64;       // warp col base

    // A staging mapping (rows ar, ar+64)
    int ar = tid >> 2;              // 0..63
    int ak = (tid & 3) * 4;         // 0,4,8,12
    // B cp.async mapping: 16 rows x 128 bf16 = 256 x 16B chunks
    int brow = tid >> 4;            // 0..15
    int bcol = (tid & 15) * 8;      // 0..120

    const float* Aptr = A + (size_t)(m0 + ar) * K + ak;
    const __nv_bfloat16* Bhp = Bh_g + (size_t)brow * N + n0b + bcol;
    const __nv_bfloat16* Blp = Bl_g + (size_t)brow * N + n0b + bcol;
    const size_t a64 = (size_t)64 * K;

    int lr  = lane & 15;
    int lc8 = (lane >> 4) * 8;

    float acc[2][8][4];
    #pragma unroll
    for (int i = 0; i < 2; i++)
        #pragma unroll
        for (int j = 0; j < 8; j++)
            #pragma unroll
            for (int r = 0; r < 4; r++) acc[i][j][r] = 0.f;

    // ---- prologue: B chunk 0 -> stage 0; A chunk 0 -> regs ----
    {
        unsigned d0 = (unsigned)__cvta_generic_to_shared(&Bh[0][brow][bcol]);
        unsigned d1 = (unsigned)__cvta_generic_to_shared(&Bl[0][brow][bcol]);
        CP_ASYNC16(d0, Bhp);
        CP_ASYNC16(d1, Blp);
        CP_COMMIT();
    }
    float4 pa0 = *(const float4*)(Aptr);
    float4 pa1 = *(const float4*)(Aptr + a64);

    int chunks = K >> 4;
    for (int ch = 0; ch < chunks; ch++) {
        int cur = ch & 1;
        bool more = (ch + 1 < chunks);

        // ---- split + store A chunk ch (single buffer; prev MMA reads done) ----
        {
            __nv_bfloat16 h0,l0,h1,l1,h2,l2,h3,l3;
            __nv_bfloat162 t;
            bsplit(pa0.x,h0,l0); bsplit(pa0.y,h1,l1); bsplit(pa0.z,h2,l2); bsplit(pa0.w,h3,l3);
            t.x=h0; t.y=h1; *(__nv_bfloat162*)&Ah[ar][ak]   = t;
            t.x=h2; t.y=h3; *(__nv_bfloat162*)&Ah[ar][ak+2] = t;
            t.x=l0; t.y=l1; *(__nv_bfloat162*)&Al[ar][ak]   = t;
            t.x=l2; t.y=l3; *(__nv_bfloat162*)&Al[ar][ak+2] = t;
            bsplit(pa1.x,h0,l0); bsplit(pa1.y,h1,l1); bsplit(pa1.z,h2,l2); bsplit(pa1.w,h3,l3);
            t.x=h0; t.y=h1; *(__nv_bfloat162*)&Ah[ar+64][ak]   = t;
            t.x=h2; t.y=h3; *(__nv_bfloat162*)&Ah[ar+64][ak+2] = t;
            t.x=l0; t.y=l1; *(__nv_bfloat162*)&Al[ar+64][ak]   = t;
            t.x=l2; t.y=l3; *(__nv_bfloat162*)&Al[ar+64][ak+2] = t;
        }
        CP_WAIT0();          // B chunk ch landed in stage cur
        __syncthreads();

        if (more) {
            // prefetch A chunk ch+1 into regs (LDG overlaps MMA)
            Aptr += 16;
            pa0 = *(const float4*)(Aptr);
            pa1 = *(const float4*)(Aptr + a64);
            // kick B chunk ch+1 into stage cur^1 (cp.async overlaps MMA)
            Bhp += (size_t)16 * N;
            Blp += (size_t)16 * N;
            unsigned d0 = (unsigned)__cvta_generic_to_shared(&Bh[cur^1][brow][bcol]);
            unsigned d1 = (unsigned)__cvta_generic_to_shared(&Bl[cur^1][brow][bcol]);
            CP_ASYNC16(d0, Bhp);
            CP_ASYNC16(d1, Blp);
            CP_COMMIT();
        }

        // ---- A fragments ----
        unsigned a_h[2][4], a_l[2][4];
        #pragma unroll
        for (int mi = 0; mi < 2; mi++) {
            unsigned ad = (unsigned)__cvta_generic_to_shared(&Ah[rm + 16*mi + lr][lc8]);
            LDSM_X4(a_h[mi], ad);
            ad = (unsigned)__cvta_generic_to_shared(&Al[rm + 16*mi + lr][lc8]);
            LDSM_X4(a_l[mi], ad);
        }

        // ---- B fragments + mma ----
        #pragma unroll
        for (int np = 0; np < 4; np++) {
            int ncol = rn + np * 16;
            unsigned b_h[4], b_l[4];
            unsigned bd = (unsigned)__cvta_generic_to_shared(&Bh[cur][lr][ncol + lc8]);
            LDSM_X4_T(b_h, bd);
            bd = (unsigned)__cvta_generic_to_shared(&Bl[cur][lr][ncol + lc8]);
            LDSM_X4_T(b_l, bd);
            #pragma unroll
            for (int mi = 0; mi < 2; mi++) {
                float* d0 = acc[mi][2*np];
                float* d1 = acc[mi][2*np + 1];
                MMA_BF16(d0, a_h[mi], b_h[0], b_h[1]);
                MMA_BF16(d0, a_h[mi], b_l[0], b_l[1]);
                MMA_BF16(d0, a_l[mi], b_h[0], b_h[1]);
                MMA_BF16(d1, a_h[mi], b_h[2], b_h[3]);
                MMA_BF16(d1, a_h[mi], b_l[2], b_l[3]);
                MMA_BF16(d1, a_l[mi], b_h[2], b_h[3]);
            }
        }
        __syncthreads();     // A buffer free for next chunk's stores
    }

    // ---- epilogue ----
    int g  = lane >> 2;
    int t2 = (lane & 3) * 2;
    #pragma unroll
    for (int mi = 0; mi < 2; mi++) {
        #pragma unroll
        for (int ni = 0; ni < 8; ni++) {
            int col = n0b + rn + 8*ni + t2;
            size_t r0 = (size_t)(m0 + rm + 16*mi + g);
            size_t r1 = r0 + 8;
            float v0 = acc[mi][ni][0], v1 = acc[mi][ni][1];
            float v2 = acc[mi][ni][2], v3 = acc[mi][ni][3];
            if (BIAS) { float b0 = bias[col], b1 = bias[col+1]; v0 += b0; v1 += b1; v2 += b0; v3 += b1; }
            if (RELU) { v0 = fmaxf(v0,0.f); v1 = fmaxf(v1,0.f); v2 = fmaxf(v2,0.f); v3 = fmaxf(v3,0.f); }
            *(float2*)&C[r0*N + col] = make_float2(v0, v1);
            *(float2*)&C[r1*N + col] = make_float2(v2, v3);
        }
    }
}

// ---------------- fused windowed attention (no-max single-pass softmax) ----
__global__ void attn_win_k(const float* __restrict__ Q, const float* __restrict__ K,
                           const float* __restrict__ V, float* __restrict__ O,
                           int Hq, int Wq, int Hk, int Wk, int strideK) {
    int wW = Wq >> 3, wH = Hq >> 3;
    int b    = blockIdx.x;
    int head = blockIdx.y;
    int ww = b % wW; int t1 = b / wW;
    int wh = t1 % wH; int n  = t1 / wH;
    int t = threadIdx.x;

    __shared__ __align__(16) float Ks[64][36];
    __shared__ __align__(16) float Vs[64][36];

    {
        int ki = t >> 3, kj = t & 7;
        int rk = (wh * strideK + ki) % Hk;
        int ck = (ww * strideK + kj) % Wk;
        size_t kb = ((size_t)(n*Hk + rk)*Wk + ck) * CCH + head*DH;
        #pragma unroll
        for (int c = 0; c < DH; c += 4) {
            *(float4*)&Ks[t][c] = *(const float4*)&K[kb + c];
            *(float4*)&Vs[t][c] = *(const float4*)&V[kb + c];
        }
    }
    int rq = wh*8 + (t >> 3), cq = ww*8 + (t & 7);
    size_t qb = ((size_t)(n*Hq + rq)*Wq + cq) * CCH + head*DH;
    float4 q4[8];
    #pragma unroll
    for (int c = 0; c < 8; c++) q4[c] = *(const float4*)&Q[qb + c*4];
    __syncthreads();

    const float scale = 0.17677669529663687f;  // 1/sqrt(32)
    float4 acc[8];
    #pragma unroll
    for (int c = 0; c < 8; c++) acc[c] = make_float4(0.f, 0.f, 0.f, 0.f);
    float sum = 0.f;

    #pragma unroll 4
    for (int j = 0; j < 64; j++) {
        float d = 0.f;
        #pragma unroll
        for (int c = 0; c < 8; c++) {
            float4 kk = *(const float4*)&Ks[j][c*4];
            d += q4[c].x*kk.x + q4[c].y*kk.y + q4[c].z*kk.z + q4[c].w*kk.w;
        }
        float e = __expf(d * scale);
        sum += e;
        #pragma unroll
        for (int c = 0; c < 8; c++) {
            float4 vv = *(const float4*)&Vs[j][c*4];
            acc[c].x += e*vv.x; acc[c].y += e*vv.y; acc[c].z += e*vv.z; acc[c].w += e*vv.w;
        }
    }
    float inv = 1.f / sum;
    #pragma unroll
    for (int c = 0; c < 8; c++) {
        float4 o = make_float4(acc[c].x*inv, acc[c].y*inv, acc[c].z*inv, acc[c].w*inv);
        *(float4*)&O[qb + c*4] = o;
    }
}

// ---------------- fused residual-add + layernorm (C=256) -----------------
__global__ void add_ln_k(const float* __restrict__ X, const float* __restrict__ P,
                         const float* __restrict__ g, const float* __restrict__ b,
                         float* __restrict__ out) {
    int tok = blockIdx.x;
    int c   = threadIdx.x;
    size_t idx = (size_t)tok * CCH + c;
    float v = X[idx] + P[idx];

    __shared__ float red[8];
    float s = v;
    #pragma unroll
    for (int o = 16; o; o >>= 1) s += __shfl_xor_sync(0xffffffffu, s, o);
    if ((c & 31) == 0) red[c >> 5] = s;
    __syncthreads();
    float mu = 0.f;
    #pragma unroll
    for (int i = 0; i < 8; i++) mu += red[i];
    mu *= (1.f / CCH);

    float d  = v - mu;
    float s2 = d * d;
    #pragma unroll
    for (int o = 16; o; o >>= 1) s2 += __shfl_xor_sync(0xffffffffu, s2, o);
    __syncthreads();
    if ((c & 31) == 0) red[c >> 5] = s2;
    __syncthreads();
    float var = 0.f;
    #pragma unroll
    for (int i = 0; i < 8; i++) var += red[i];
    var *= (1.f / CCH);

    out[idx] = d * rsqrtf(var + 1e-5f) * g[c] + b[c];
}

// ---------------- 4x4 average pool (128x128 -> 32x32) --------------------
__global__ void avgpool_k(const float* __restrict__ in, float* __restrict__ out) {
    int i = blockIdx.x * blockDim.x + threadIdx.x;
    if (i >= TOK1 * CCH) return;
    int c    = i & (CCH - 1);
    int toko = i >> 8;
    int ow = toko & 31; int t = toko >> 5;
    int oh = t & 31;    int n = t >> 5;
    float s = 0.f;
    #pragma unroll
    for (int di = 0; di < 4; di++)
        #pragma unroll
        for (int dj = 0; dj < 4; dj++)
            s += in[((size_t)(n*HH + oh*4 + di)*WW2 + ow*4 + dj)*CCH + c];
    out[i] = s * (1.f / 16.f);
}

// ---------------- host orchestration -------------------------------------
static __nv_bfloat16 *h_wh = nullptr, *h_wl = nullptr;

static inline void run_gemm(const float* A, const __nv_bfloat16* Bh, const __nv_bfloat16* Bl,
                            const float* bias, float* C, int M, int N, int K, bool relu) {
    dim3 grid(N / 128, M / 128);
    if (relu)       gemm_mma_k<true,  true ><<<grid, 256>>>(A, Bh, Bl, bias, C, M, N, K);
    else if (bias)  gemm_mma_k<false, true ><<<grid, 256>>>(A, Bh, Bl, bias, C, M, N, K);
    else            gemm_mma_k<false, false><<<grid, 256>>>(A, Bh, Bl, bias, C, M, N, K);
}

extern "C" void kernel_launch(void* const* d_in, const int* in_sizes, int n_in,
                              void* d_out, int out_size) {
    const float* x        = (const float*)d_in[0];
    const float* sa_wq    = (const float*)d_in[1];
    const float* sa_wk    = (const float*)d_in[2];
    const float* sa_wv    = (const float*)d_in[3];
    const float* sa_wf    = (const float*)d_in[4];
    const float* sa_bf    = (const float*)d_in[5];
    const float* ca_wq    = (const float*)d_in[6];
    const float* ca_wk    = (const float*)d_in[7];
    const float* ca_wv    = (const float*)d_in[8];
    const float* ca_wf    = (const float*)d_in[9];
    const float* ca_bf    = (const float*)d_in[10];
    const float* ln_s_g   = (const float*)d_in[11];
    const float* ln_s_b   = (const float*)d_in[12];
    const float* ln_c_g   = (const float*)d_in[13];
    const float* ln_c_b   = (const float*)d_in[14];
    const float* ffn_w1   = (const float*)d_in[15];
    const float* ffn_b1   = (const float*)d_in[16];
    const float* ffn_w2   = (const float*)d_in[17];
    const float* ffn_b2   = (const float*)d_in[18];
    const float* ln_o_g   = (const float*)d_in[19];
    const float* ln_o_b   = (const float*)d_in[20];

    float *xh, *q, *k, *v, *attn, *proj, *l0, *lc, *hid;
    float *pool, *q1, *k1, *v1, *a1, *p1, *l1;
    cudaGetSymbolAddress((void**)&xh,   g_xh);
    cudaGetSymbolAddress((void**)&q,    g_q);
    cudaGetSymbolAddress((void**)&k,    g_k);
    cudaGetSymbolAddress((void**)&v,    g_v);
    cudaGetSymbolAddress((void**)&attn, g_attn);
    cudaGetSymbolAddress((void**)&proj, g_proj);
    cudaGetSymbolAddress((void**)&l0,   g_l0);
    cudaGetSymbolAddress((void**)&lc,   g_lc);
    cudaGetSymbolAddress((void**)&hid,  g_hid);
    cudaGetSymbolAddress((void**)&pool, g_pool);
    cudaGetSymbolAddress((void**)&q1,   g_q1);
    cudaGetSymbolAddress((void**)&k1,   g_k1);
    cudaGetSymbolAddress((void**)&v1,   g_v1);
    cudaGetSymbolAddress((void**)&a1,   g_a1);
    cudaGetSymbolAddress((void**)&p1,   g_p1);
    cudaGetSymbolAddress((void**)&l1,   g_l1);
    cudaGetSymbolAddress((void**)&h_wh, g_wh);
    cudaGetSymbolAddress((void**)&h_wl, g_wl);

    // ---- split all 10 weight matrices into bf16 hi/lo (one launch) ----
    WJobs jobs;
    jobs.p[0] = sa_wq; jobs.p[1] = sa_wk; jobs.p[2] = sa_wv; jobs.p[3] = sa_wf;
    jobs.p[4] = ca_wq; jobs.p[5] = ca_wk; jobs.p[6] = ca_wv; jobs.p[7] = ca_wf;
    jobs.p[8] = ffn_w1; jobs.p[9] = ffn_w2;
    wsplit_all_k<<<WTOT/256, 256>>>(jobs, h_wh, h_wl);

    dim3 tb(32, 8);
    transpose_in_k<<<dim3(HWP/32, CCH/32, NB), tb>>>(x, xh);

    // ---- level-0 self-attention (128x128) ----
    run_gemm(xh, h_wh+OFF_SAWQ, h_wl+OFF_SAWQ, nullptr, q, TOK0, CCH, CCH, false);
    run_gemm(xh, h_wh+OFF_SAWK, h_wl+OFF_SAWK, nullptr, k, TOK0, CCH, CCH, false);
    run_gemm(xh, h_wh+OFF_SAWV, h_wl+OFF_SAWV, nullptr, v, TOK0, CCH, CCH, false);
    attn_win_k<<<dim3(NB*16*16, HEADS), 64>>>(q, k, v, attn, HH, WW2, HH, WW2, 8);
    run_gemm(attn, h_wh+OFF_SAWF, h_wl+OFF_SAWF, sa_bf, proj, TOK0, CCH, CCH, false);
    add_ln_k<<<TOK0, CCH>>>(xh, proj, ln_s_g, ln_s_b, l0);

    // ---- pool to 32x32 ----
    avgpool_k<<<(TOK1*CCH + 255)/256, 256>>>(l0, pool);

    // ---- level-1 self-attention (32x32) ----
    run_gemm(pool, h_wh+OFF_SAWQ, h_wl+OFF_SAWQ, nullptr, q1, TOK1, CCH, CCH, false);
    run_gemm(pool, h_wh+OFF_SAWK, h_wl+OFF_SAWK, nullptr, k1, TOK1, CCH, CCH, false);
    run_gemm(pool, h_wh+OFF_SAWV, h_wl+OFF_SAWV, nullptr, v1, TOK1, CCH, CCH, false);
    attn_win_k<<<dim3(NB*4*4, HEADS), 64>>>(q1, k1, v1, a1, H1, H1, H1, H1, 8);
    run_gemm(a1, h_wh+OFF_SAWF, h_wl+OFF_SAWF, sa_bf, p1, TOK1, CCH, CCH, false);
    add_ln_k<<<TOK1, CCH>>>(pool, p1, ln_s_g, ln_s_b, l1);

    // ---- cross-attention: q = l0 (128x128), kv = l1 (32x32, stride-2 circular)
    run_gemm(l0, h_wh+OFF_CAWQ, h_wl+OFF_CAWQ, nullptr, q,  TOK0, CCH, CCH, false);
    run_gemm(l1, h_wh+OFF_CAWK, h_wl+OFF_CAWK, nullptr, k1, TOK1, CCH, CCH, false);
    run_gemm(l1, h_wh+OFF_CAWV, h_wl+OFF_CAWV, nullptr, v1, TOK1, CCH, CCH, false);
    attn_win_k<<<dim3(NB*16*16, HEADS), 64>>>(q, k1, v1, attn, HH, WW2, H1, H1, 2);
    run_gemm(attn, h_wh+OFF_CAWF, h_wl+OFF_CAWF, ca_bf, proj, TOK0, CCH, CCH, false);
    add_ln_k<<<TOK0, CCH>>>(l0, proj, ln_c_g, ln_c_b, lc);

    // ---- FFN 256 -> 1024 (relu) -> 256, then residual + LN ----
    run_gemm(lc,  h_wh+OFF_FFN1, h_wl+OFF_FFN1, ffn_b1, hid,  TOK0, DF,  CCH, true);
    run_gemm(hid, h_wh+OFF_FFN2, h_wl+OFF_FFN2, ffn_b2, proj, TOK0, CCH, DF,  false);
    add_ln_k<<<TOK0, CCH>>>(lc, proj, ln_o_g, ln_o_b, attn);

    // NHWC -> NCHW
    transpose_out_k<<<dim3(HWP/32, CCH/32, NB), tb>>>(attn, (float*)d_out);
}

// round 17
// speedup vs baseline: 1.5036x; 1.5036x over previous
#include <cuda_runtime.h>
#include <cuda_bf16.h>
#include <math.h>

// ---------------- problem constants ----------------
#define NB    8
#define CCH   256
#define HH    128
#define WW2   128
#define HWP   (HH*WW2)          // 16384
#define TOK0  (NB*HH*WW2)       // 131072 tokens level-0
#define H1    32
#define TOK1  (NB*H1*H1)        // 8192 tokens level-1
#define HEADS 8
#define DH    32
#define DF    1024

// ---------------- device scratch (static; allocation-free) ----------------
__device__ float g_xh   [(size_t)TOK0*CCH];
__device__ float g_q    [(size_t)TOK0*CCH];
__device__ float g_k    [(size_t)TOK0*CCH];
__device__ float g_v    [(size_t)TOK0*CCH];
__device__ float g_attn [(size_t)TOK0*CCH];
__device__ float g_proj [(size_t)TOK0*CCH];
__device__ float g_l0   [(size_t)TOK0*CCH];
__device__ float g_lc   [(size_t)TOK0*CCH];
__device__ float g_hid  [(size_t)TOK0*DF];
__device__ float g_pool [(size_t)TOK1*CCH];
__device__ float g_q1   [(size_t)TOK1*CCH];
__device__ float g_k1   [(size_t)TOK1*CCH];
__device__ float g_v1   [(size_t)TOK1*CCH];
__device__ float g_a1   [(size_t)TOK1*CCH];
__device__ float g_p1   [(size_t)TOK1*CCH];
__device__ float g_l1   [(size_t)TOK1*CCH];

// ---------------- transposes (NCHW <-> NHWC) ----------------
__global__ void transpose_in_k(const float* __restrict__ in, float* __restrict__ out) {
    __shared__ float tile[32][33];
    int n  = blockIdx.z;
    int p0 = blockIdx.x * 32;
    int c0 = blockIdx.y * 32;
    for (int j = threadIdx.y; j < 32; j += 8)
        tile[j][threadIdx.x] = in[((size_t)(n*CCH + c0 + j))*HWP + p0 + threadIdx.x];
    __syncthreads();
    for (int j = threadIdx.y; j < 32; j += 8)
        out[((size_t)(n*HWP + p0 + j))*CCH + c0 + threadIdx.x] = tile[threadIdx.x][j];
}

// ---------------- bf16x3 split-precision tensor-core GEMM ------------------
// R14-benched design (157us/big-GEMM) + 8B-packed staging stores.
// C[M,N] = A[M,K] @ B[K,N] (+bias)(+relu), fp32-accurate via bf16 hi/lo split:
//   a*b ~= ah*bh + ah*bl + al*bh   (drops al*bl ~ 2^-18 relative)

#define LDSM_X4(r, addr) \
    asm volatile("ldmatrix.sync.aligned.m8n8.x4.shared.b16 {%0,%1,%2,%3}, [%4];" \
        : "=r"(r[0]), "=r"(r[1]), "=r"(r[2]), "=r"(r[3]) : "r"(addr))

#define LDSM_X4_T(r, addr) \
    asm volatile("ldmatrix.sync.aligned.m8n8.x4.trans.shared.b16 {%0,%1,%2,%3}, [%4];" \
        : "=r"(r[0]), "=r"(r[1]), "=r"(r[2]), "=r"(r[3]) : "r"(addr))

#define MMA_BF16(d, a, b0_, b1_) \
    asm volatile("mma.sync.aligned.m16n8k16.row.col.f32.bf16.bf16.f32 " \
        "{%0,%1,%2,%3}, {%4,%5,%6,%7}, {%8,%9}, {%0,%1,%2,%3};" \
        : "+f"(d[0]), "+f"(d[1]), "+f"(d[2]), "+f"(d[3]) \
        : "r"(a[0]), "r"(a[1]), "r"(a[2]), "r"(a[3]), "r"(b0_), "r"(b1_))

__device__ __forceinline__ void bsplit(float x, __nv_bfloat16& h, __nv_bfloat16& l) {
    h = __float2bfloat16(x);
    l = __float2bfloat16(x - __bfloat162float(h));
}

__device__ __forceinline__ unsigned pack2(__nv_bfloat16 a, __nv_bfloat16 b) {
    __nv_bfloat162 t; t.x = a; t.y = b;
    return *(unsigned*)&t;
}

#define A_STRIDE 24    // 16 used + 8 pad bf16 -> 48B rows, conflict-free ldmatrix
#define B_STRIDE 136   // 128 used + 8 pad bf16 -> 272B rows, conflict-free ldmatrix.trans

template<bool RELU, bool BIAS>
__global__ __launch_bounds__(256, 2)
void gemm_mma_k(const float* __restrict__ A, const float* __restrict__ B,
                const float* __restrict__ bias, float* __restrict__ C,
                int M, int N, int K) {
    __shared__ __align__(16) __nv_bfloat16 Ah[128][A_STRIDE];
    __shared__ __align__(16) __nv_bfloat16 Al[128][A_STRIDE];
    __shared__ __align__(16) __nv_bfloat16 Bh[16][B_STRIDE];
    __shared__ __align__(16) __nv_bfloat16 Bl[16][B_STRIDE];

    int tid  = threadIdx.x;
    int lane = tid & 31;
    int wid  = tid >> 5;
    int m0 = blockIdx.y * 128, n0b = blockIdx.x * 128;

    int rm = (wid & 3) * 32;        // warp row base
    int rn = (wid >> 2) * 64;       // warp col base

    int ar = tid >> 2;              // 0..63  (rows ar, ar+64)
    int ak = (tid & 3) * 4;         // 0,4,8,12
    int br = tid >> 5;              // 0..7   (rows br, br+8)
    int bc = (tid & 31) * 4;        // 0..124

    const float* Aptr = A + (size_t)(m0 + ar) * K + ak;
    const float* Bptr = B + (size_t)br * N + n0b + bc;
    const size_t a64 = (size_t)64 * K;
    const size_t b8  = (size_t)8 * N;

    int lr  = lane & 15;
    int lc8 = (lane >> 4) * 8;

    float acc[2][8][4];
    #pragma unroll
    for (int i = 0; i < 2; i++)
        #pragma unroll
        for (int j = 0; j < 8; j++)
            #pragma unroll
            for (int r = 0; r < 4; r++) acc[i][j][r] = 0.f;

    float4 pa0 = *(const float4*)(Aptr);
    float4 pa1 = *(const float4*)(Aptr + a64);
    float4 pb0 = *(const float4*)(Bptr);
    float4 pb1 = *(const float4*)(Bptr + b8);

    int chunks = K >> 4;
    for (int ch = 0; ch < chunks; ch++) {
        // ---- stage + split to smem (8B packed stores) ----
        {
            __nv_bfloat16 h0,l0,h1,l1,h2,l2,h3,l3;
            bsplit(pa0.x,h0,l0); bsplit(pa0.y,h1,l1); bsplit(pa0.z,h2,l2); bsplit(pa0.w,h3,l3);
            *(uint2*)&Ah[ar][ak] = make_uint2(pack2(h0,h1), pack2(h2,h3));
            *(uint2*)&Al[ar][ak] = make_uint2(pack2(l0,l1), pack2(l2,l3));
            bsplit(pa1.x,h0,l0); bsplit(pa1.y,h1,l1); bsplit(pa1.z,h2,l2); bsplit(pa1.w,h3,l3);
            *(uint2*)&Ah[ar+64][ak] = make_uint2(pack2(h0,h1), pack2(h2,h3));
            *(uint2*)&Al[ar+64][ak] = make_uint2(pack2(l0,l1), pack2(l2,l3));
            bsplit(pb0.x,h0,l0); bsplit(pb0.y,h1,l1); bsplit(pb0.z,h2,l2); bsplit(pb0.w,h3,l3);
            *(uint2*)&Bh[br][bc] = make_uint2(pack2(h0,h1), pack2(h2,h3));
            *(uint2*)&Bl[br][bc] = make_uint2(pack2(l0,l1), pack2(l2,l3));
            bsplit(pb1.x,h0,l0); bsplit(pb1.y,h1,l1); bsplit(pb1.z,h2,l2); bsplit(pb1.w,h3,l3);
            *(uint2*)&Bh[br+8][bc] = make_uint2(pack2(h0,h1), pack2(h2,h3));
            *(uint2*)&Bl[br+8][bc] = make_uint2(pack2(l0,l1), pack2(l2,l3));
        }
        __syncthreads();

        if (ch + 1 < chunks) {   // prefetch next global tile
            Aptr += 16;
            Bptr += (size_t)16 * N;
            pa0 = *(const float4*)(Aptr);
            pa1 = *(const float4*)(Aptr + a64);
            pb0 = *(const float4*)(Bptr);
            pb1 = *(const float4*)(Bptr + b8);
        }

        // ---- A fragments ----
        unsigned a_h[2][4], a_l[2][4];
        #pragma unroll
        for (int mi = 0; mi < 2; mi++) {
            unsigned ad = (unsigned)__cvta_generic_to_shared(&Ah[rm + 16*mi + lr][lc8]);
            LDSM_X4(a_h[mi], ad);
            ad = (unsigned)__cvta_generic_to_shared(&Al[rm + 16*mi + lr][lc8]);
            LDSM_X4(a_l[mi], ad);
        }

        // ---- B fragments + mma ----
        #pragma unroll
        for (int np = 0; np < 4; np++) {
            int ncol = rn + np * 16;
            unsigned b_h[4], b_l[4];
            unsigned bd = (unsigned)__cvta_generic_to_shared(&Bh[lr][ncol + lc8]);
            LDSM_X4_T(b_h, bd);
            bd = (unsigned)__cvta_generic_to_shared(&Bl[lr][ncol + lc8]);
            LDSM_X4_T(b_l, bd);
            #pragma unroll
            for (int mi = 0; mi < 2; mi++) {
                float* d0 = acc[mi][2*np];
                float* d1 = acc[mi][2*np + 1];
                MMA_BF16(d0, a_h[mi], b_h[0], b_h[1]);
                MMA_BF16(d0, a_h[mi], b_l[0], b_l[1]);
                MMA_BF16(d0, a_l[mi], b_h[0], b_h[1]);
                MMA_BF16(d1, a_h[mi], b_h[2], b_h[3]);
                MMA_BF16(d1, a_h[mi], b_l[2], b_l[3]);
                MMA_BF16(d1, a_l[mi], b_h[2], b_h[3]);
            }
        }
        __syncthreads();
    }

    // ---- epilogue ----
    int g  = lane >> 2;
    int t2 = (lane & 3) * 2;
    #pragma unroll
    for (int mi = 0; mi < 2; mi++) {
        #pragma unroll
        for (int ni = 0; ni < 8; ni++) {
            int col = n0b + rn + 8*ni + t2;
            size_t r0 = (size_t)(m0 + rm + 16*mi + g);
            size_t r1 = r0 + 8;
            float v0 = acc[mi][ni][0], v1 = acc[mi][ni][1];
            float v2 = acc[mi][ni][2], v3 = acc[mi][ni][3];
            if (BIAS) { float b0 = bias[col], b1 = bias[col+1]; v0 += b0; v1 += b1; v2 += b0; v3 += b1; }
            if (RELU) { v0 = fmaxf(v0,0.f); v1 = fmaxf(v1,0.f); v2 = fmaxf(v2,0.f); v3 = fmaxf(v3,0.f); }
            *(float2*)&C[r0*N + col] = make_float2(v0, v1);
            *(float2*)&C[r1*N + col] = make_float2(v2, v3);
        }
    }
}

// ---------------- fused windowed attention (no-max single-pass softmax) ----
__global__ void attn_win_k(const float* __restrict__ Q, const float* __restrict__ K,
                           const float* __restrict__ V, float* __restrict__ O,
                           int Hq, int Wq, int Hk, int Wk, int strideK) {
    int wW = Wq >> 3, wH = Hq >> 3;
    int b    = blockIdx.x;
    int head = blockIdx.y;
    int ww = b % wW; int t1 = b / wW;
    int wh = t1 % wH; int n  = t1 / wH;
    int t = threadIdx.x;

    __shared__ __align__(16) float Ks[64][36];
    __shared__ __align__(16) float Vs[64][36];

    {
        int ki = t >> 3, kj = t & 7;
        int rk = (wh * strideK + ki) % Hk;
        int ck = (ww * strideK + kj) % Wk;
        size_t kb = ((size_t)(n*Hk + rk)*Wk + ck) * CCH + head*DH;
        #pragma unroll
        for (int c = 0; c < DH; c += 4) {
            *(float4*)&Ks[t][c] = *(const float4*)&K[kb + c];
            *(float4*)&Vs[t][c] = *(const float4*)&V[kb + c];
        }
    }
    int rq = wh*8 + (t >> 3), cq = ww*8 + (t & 7);
    size_t qb = ((size_t)(n*Hq + rq)*Wq + cq) * CCH + head*DH;
    float4 q4[8];
    #pragma unroll
    for (int c = 0; c < 8; c++) q4[c] = *(const float4*)&Q[qb + c*4];
    __syncthreads();

    const float scale = 0.17677669529663687f;  // 1/sqrt(32)
    float4 acc[8];
    #pragma unroll
    for (int c = 0; c < 8; c++) acc[c] = make_float4(0.f, 0.f, 0.f, 0.f);
    float sum = 0.f;

    #pragma unroll 4
    for (int j = 0; j < 64; j++) {
        float d = 0.f;
        #pragma unroll
        for (int c = 0; c < 8; c++) {
            float4 kk = *(const float4*)&Ks[j][c*4];
            d += q4[c].x*kk.x + q4[c].y*kk.y + q4[c].z*kk.z + q4[c].w*kk.w;
        }
        float e = __expf(d * scale);
        sum += e;
        #pragma unroll
        for (int c = 0; c < 8; c++) {
            float4 vv = *(const float4*)&Vs[j][c*4];
            acc[c].x += e*vv.x; acc[c].y += e*vv.y; acc[c].z += e*vv.z; acc[c].w += e*vv.w;
        }
    }
    float inv = 1.f / sum;
    #pragma unroll
    for (int c = 0; c < 8; c++) {
        float4 o = make_float4(acc[c].x*inv, acc[c].y*inv, acc[c].z*inv, acc[c].w*inv);
        *(float4*)&O[qb + c*4] = o;
    }
}

// ---------------- fused residual-add + layernorm (C=256) -----------------
__global__ void add_ln_k(const float* __restrict__ X, const float* __restrict__ P,
                         const float* __restrict__ g, const float* __restrict__ b,
                         float* __restrict__ out) {
    int tok = blockIdx.x;
    int c   = threadIdx.x;
    size_t idx = (size_t)tok * CCH + c;
    float v = X[idx] + P[idx];

    __shared__ float red[8];
    float s = v;
    #pragma unroll
    for (int o = 16; o; o >>= 1) s += __shfl_xor_sync(0xffffffffu, s, o);
    if ((c & 31) == 0) red[c >> 5] = s;
    __syncthreads();
    float mu = 0.f;
    #pragma unroll
    for (int i = 0; i < 8; i++) mu += red[i];
    mu *= (1.f / CCH);

    float d  = v - mu;
    float s2 = d * d;
    #pragma unroll
    for (int o = 16; o; o >>= 1) s2 += __shfl_xor_sync(0xffffffffu, s2, o);
    __syncthreads();
    if ((c & 31) == 0) red[c >> 5] = s2;
    __syncthreads();
    float var = 0.f;
    #pragma unroll
    for (int i = 0; i < 8; i++) var += red[i];
    var *= (1.f / CCH);

    out[idx] = d * rsqrtf(var + 1e-5f) * g[c] + b[c];
}

// ---------------- fused add + LN + NHWC->NCHW transpose (final stage) -----
// Block: 32 spatial positions x full 256 channels of one batch image.
// out[n][c][p] = LN(X[n][p][:] + P[n][p][:])[c]
__global__ void add_ln_tr_out_k(const float* __restrict__ X, const float* __restrict__ P,
                                const float* __restrict__ g, const float* __restrict__ b,
                                float* __restrict__ out) {
    __shared__ float buf[32][257];
    __shared__ float mus[32], rss[32];
    int p0  = blockIdx.x * 32;
    int n   = blockIdx.y;
    int tid = threadIdx.x;      // 256 threads
    int lane = tid & 31, wid = tid >> 5;

    // phase 1: load+add 32 token rows (one row per iteration, coalesced)
    size_t base = ((size_t)n * HWP + p0) * CCH;
    #pragma unroll 4
    for (int it = 0; it < 32; it++) {
        size_t idx = base + (size_t)it * CCH + tid;
        buf[it][tid] = X[idx] + P[idx];
    }
    __syncthreads();

    // phase 2: per-token LN stats; warp w handles tokens w, w+8, w+16, w+24
    for (int tk = wid; tk < 32; tk += 8) {
        float s = 0.f, s2 = 0.f;
        #pragma unroll
        for (int k = 0; k < 8; k++) {
            float v = buf[tk][lane + 32*k];
            s += v; s2 += v*v;
        }
        #pragma unroll
        for (int o = 16; o; o >>= 1) {
            s  += __shfl_xor_sync(0xffffffffu, s,  o);
            s2 += __shfl_xor_sync(0xffffffffu, s2, o);
        }
        if (lane == 0) {
            float mu  = s * (1.f / CCH);
            float var = s2 * (1.f / CCH) - mu*mu;
            mus[tk] = mu;
            rss[tk] = rsqrtf(var + 1e-5f);
        }
    }
    __syncthreads();

    // phase 3: transposed coalesced writes; warp row = 32 consecutive p for one c
    // thread (lane=p-offset, wid + 8*cc = channel)
    for (int cc = 0; cc < 32; cc++) {
        int c = wid + 8*cc;
        float v = (buf[lane][c] - mus[lane]) * rss[lane] * g[c] + b[c];
        out[((size_t)(n*CCH + c))*HWP + p0 + lane] = v;
    }
}

// ---------------- 4x4 average pool (128x128 -> 32x32) --------------------
__global__ void avgpool_k(const float* __restrict__ in, float* __restrict__ out) {
    int i = blockIdx.x * blockDim.x + threadIdx.x;
    if (i >= TOK1 * CCH) return;
    int c    = i & (CCH - 1);
    int toko = i >> 8;
    int ow = toko & 31; int t = toko >> 5;
    int oh = t & 31;    int n = t >> 5;
    float s = 0.f;
    #pragma unroll
    for (int di = 0; di < 4; di++)
        #pragma unroll
        for (int dj = 0; dj < 4; dj++)
            s += in[((size_t)(n*HH + oh*4 + di)*WW2 + ow*4 + dj)*CCH + c];
    out[i] = s * (1.f / 16.f);
}

// ---------------- host orchestration -------------------------------------
static inline void run_gemm(const float* A, const float* B, const float* bias,
                            float* C, int M, int N, int K, bool relu) {
    dim3 grid(N / 128, M / 128);
    if (relu)       gemm_mma_k<true,  true ><<<grid, 256>>>(A, B, bias, C, M, N, K);
    else if (bias)  gemm_mma_k<false, true ><<<grid, 256>>>(A, B, bias, C, M, N, K);
    else            gemm_mma_k<false, false><<<grid, 256>>>(A, B, bias, C, M, N, K);
}

extern "C" void kernel_launch(void* const* d_in, const int* in_sizes, int n_in,
                              void* d_out, int out_size) {
    const float* x        = (const float*)d_in[0];
    const float* sa_wq    = (const float*)d_in[1];
    const float* sa_wk    = (const float*)d_in[2];
    const float* sa_wv    = (const float*)d_in[3];
    const float* sa_wf    = (const float*)d_in[4];
    const float* sa_bf    = (const float*)d_in[5];
    const float* ca_wq    = (const float*)d_in[6];
    const float* ca_wk    = (const float*)d_in[7];
    const float* ca_wv    = (const float*)d_in[8];
    const float* ca_wf    = (const float*)d_in[9];
    const float* ca_bf    = (const float*)d_in[10];
    const float* ln_s_g   = (const float*)d_in[11];
    const float* ln_s_b   = (const float*)d_in[12];
    const float* ln_c_g   = (const float*)d_in[13];
    const float* ln_c_b   = (const float*)d_in[14];
    const float* ffn_w1   = (const float*)d_in[15];
    const float* ffn_b1   = (const float*)d_in[16];
    const float* ffn_w2   = (const float*)d_in[17];
    const float* ffn_b2   = (const float*)d_in[18];
    const float* ln_o_g   = (const float*)d_in[19];
    const float* ln_o_b   = (const float*)d_in[20];

    float *xh, *q, *k, *v, *attn, *proj, *l0, *lc, *hid;
    float *pool, *q1, *k1, *v1, *a1, *p1, *l1;
    cudaGetSymbolAddress((void**)&xh,   g_xh);
    cudaGetSymbolAddress((void**)&q,    g_q);
    cudaGetSymbolAddress((void**)&k,    g_k);
    cudaGetSymbolAddress((void**)&v,    g_v);
    cudaGetSymbolAddress((void**)&attn, g_attn);
    cudaGetSymbolAddress((void**)&proj, g_proj);
    cudaGetSymbolAddress((void**)&l0,   g_l0);
    cudaGetSymbolAddress((void**)&lc,   g_lc);
    cudaGetSymbolAddress((void**)&hid,  g_hid);
    cudaGetSymbolAddress((void**)&pool, g_pool);
    cudaGetSymbolAddress((void**)&q1,   g_q1);
    cudaGetSymbolAddress((void**)&k1,   g_k1);
    cudaGetSymbolAddress((void**)&v1,   g_v1);
    cudaGetSymbolAddress((void**)&a1,   g_a1);
    cudaGetSymbolAddress((void**)&p1,   g_p1);
    cudaGetSymbolAddress((void**)&l1,   g_l1);

    dim3 tb(32, 8);
    // NCHW -> NHWC
    transpose_in_k<<<dim3(HWP/32, CCH/32, NB), tb>>>(x, xh);

    // ---- level-0 self-attention (128x128) ----
    run_gemm(xh, sa_wq, nullptr, q, TOK0, CCH, CCH, false);
    run_gemm(xh, sa_wk, nullptr, k, TOK0, CCH, CCH, false);
    run_gemm(xh, sa_wv, nullptr, v, TOK0, CCH, CCH, false);
    attn_win_k<<<dim3(NB*16*16, HEADS), 64>>>(q, k, v, attn, HH, WW2, HH, WW2, 8);
    run_gemm(attn, sa_wf, sa_bf, proj, TOK0, CCH, CCH, false);
    add_ln_k<<<TOK0, CCH>>>(xh, proj, ln_s_g, ln_s_b, l0);

    // ---- pool to 32x32 ----
    avgpool_k<<<(TOK1*CCH + 255)/256, 256>>>(l0, pool);

    // ---- level-1 self-attention (32x32) ----
    run_gemm(pool, sa_wq, nullptr, q1, TOK1, CCH, CCH, false);
    run_gemm(pool, sa_wk, nullptr, k1, TOK1, CCH, CCH, false);
    run_gemm(pool, sa_wv, nullptr, v1, TOK1, CCH, CCH, false);
    attn_win_k<<<dim3(NB*4*4, HEADS), 64>>>(q1, k1, v1, a1, H1, H1, H1, H1, 8);
    run_gemm(a1, sa_wf, sa_bf, p1, TOK1, CCH, CCH, false);
    add_ln_k<<<TOK1, CCH>>>(pool, p1, ln_s_g, ln_s_b, l1);

    // ---- cross-attention: q = l0 (128x128), kv = l1 (32x32, stride-2 circular)
    run_gemm(l0, ca_wq, nullptr, q,  TOK0, CCH, CCH, false);
    run_gemm(l1, ca_wk, nullptr, k1, TOK1, CCH, CCH, false);
    run_gemm(l1, ca_wv, nullptr, v1, TOK1, CCH, CCH, false);
    attn_win_k<<<dim3(NB*16*16, HEADS), 64>>>(q, k1, v1, attn, HH, WW2, H1, H1, 2);
    run_gemm(attn, ca_wf, ca_bf, proj, TOK0, CCH, CCH, false);
    add_ln_k<<<TOK0, CCH>>>(l0, proj, ln_c_g, ln_c_b, lc);

    // ---- FFN 256 -> 1024 (relu) -> 256 ----
    run_gemm(lc,  ffn_w1, ffn_b1, hid,  TOK0, DF,  CCH, true);
    run_gemm(hid, ffn_w2, ffn_b2, proj, TOK0, CCH, DF,  false);

    // ---- fused: residual add + final LN + NHWC->NCHW transpose ----
    add_ln_tr_out_k<<<dim3(HWP/32, NB), 256>>>(lc, proj, ln_o_g, ln_o_b, (float*)d_out);
}